// round 7
// baseline (speedup 1.0000x reference)
#include <cuda_runtime.h>

// IDGNN restructured (math validated R2-R5, rel_err ~2e-7):
//   p_i = MLP_{0,i}(x);  u = x + A*p0;  d = p1 - p0
//   Un_i = u*W1e[1,i]; Dt_i = d*W1e[1,i]   (W1e[k] = w1[k]+w1[k+128])
//   S_t = sum_{n in N(t)} relu(Un0[n] + Dt0[t] + b1[1,0])
//   out[t] = u_t + self_t*d_t + S_t*w2[1,0] + deg_t*b2[1,0]
//            + self_t*( (relu(Un1_t+Dt1_t+b1[1,1])*w2[1,1]+b2[1,1])
//                      -(relu(Un0_t+Dt0_t+b1[1,0])*w2[1,0]+b2[1,0]) )
// R7 = R6 + alignment fix: the smem union must be 16B-aligned (float4 LDS/STS).
// Single launch, 128 blocks x 256 threads, 2 load-poll grid barriers,
// neighbor lists persist P2->P3, g_adj self-restored for graph replay.

#define NN 256
#define DD 128
#define NB 128
#define NT 256

// ---- device scratch (zero-init at load) ----
__device__ unsigned g_adj[NN * 8];
__device__ __align__(16) float g_W1e[2 * DD * DD];   // W1e[1][i][k][c]
__device__ __align__(16) float g_p0[NN * DD];
__device__ __align__(16) float g_p1[NN * DD];
__device__ __align__(16) float g_u [NN * DD];
__device__ __align__(16) float g_d [NN * DD];
__device__ __align__(16) float g_UD[4][NN * DD];     // 0:Un0 1:Dt0 2:Un1 3:Dt1
__device__ unsigned g_cnt;   // arrival counter (self-resets each barrier)
__device__ unsigned g_gen;   // generation (monotonic across launches)

__device__ __forceinline__ float4 f4add(float4 a, float4 b) {
    return make_float4(a.x + b.x, a.y + b.y, a.z + b.z, a.w + b.w);
}
__device__ __forceinline__ float4 f4relu(float4 a) {
    return make_float4(fmaxf(a.x, 0.f), fmaxf(a.y, 0.f),
                       fmaxf(a.z, 0.f), fmaxf(a.w, 0.f));
}
__device__ __forceinline__ unsigned ldcg_u32(const unsigned* p) {
    unsigned v;
    asm volatile("ld.global.cg.u32 %0, [%1];" : "=r"(v) : "l"(p));
    return v;
}

// Grid barrier: NB co-resident blocks. Arrive with one atomic; poll with a
// plain L2 load (no single-address atomic serialization). target = gen0 + round.
__device__ __forceinline__ void grid_sync(unsigned target) {
    __syncthreads();
    if (threadIdx.x == 0) {
        __threadfence();
        unsigned a = atomicAdd(&g_cnt, 1u);
        if (a == NB - 1) {
            atomicExch(&g_cnt, 0u);      // reset BEFORE release
            __threadfence();
            atomicExch(&g_gen, target);  // release
        } else {
            while (ldcg_u32(&g_gen) != target) __nanosleep(64);
        }
        __threadfence();
    }
    __syncthreads();
}

// Expand g_adj[row] bitmask into nbr[] (full warp). Returns count.
__device__ __forceinline__ int build_list(int row, int* nbr) {
    int lane = threadIdx.x & 31;
    unsigned word = (lane < 8) ? g_adj[row * 8 + lane] : 0u;
    int pc = __popc(word);
    int inc = pc;
#pragma unroll
    for (int off = 1; off < 8; off <<= 1) {
        int v = __shfl_up_sync(0xffffffffu, inc, off);
        if (lane >= off) inc += v;
    }
    int base = inc - pc;
    if (lane < 8) {
        unsigned bits = word; int o = base;
        while (bits) { int b = __ffs(bits) - 1; bits &= bits - 1; nbr[o++] = lane * 32 + b; }
    }
    return __shfl_sync(0xffffffffu, inc, 7);
}

struct Smem {
    int nbr[4][NN];       // persists P2 -> P3 (blocks < 64 share rows)
    int cnts[4];
    int selfS[4];
    unsigned gen0;
    __align__(16) union {    // MUST be 16B-aligned: float4 LDS/STS inside
        struct { float X[4][DD]; float H[4][DD]; } p1;                        // 4 KB
        struct { float U[4][DD]; float D[4][DD]; } p2;                        // 4 KB
        struct { float Sp[4][2][DD]; float A2[4][DD]; float Hs[2][DD]; } p3;  // 7 KB
    } u;
};

__global__ void __launch_bounds__(NT, 1)
k_fused(const int* __restrict__ ei32, int E,
        const float4* __restrict__ x4, const float* __restrict__ w1,
        const float* __restrict__ b1, const float* __restrict__ w2,
        const float* __restrict__ b2, float* __restrict__ out) {
    __shared__ Smem sm;
    const int tid = threadIdx.x, lane = tid & 31, w = tid >> 5, bid = blockIdx.x;
    const int r = w >> 1, h = w & 1;          // warp -> (row-in-block, col-half)
    const int c0 = h * 64 + lane * 2;         // this lane's 2 output columns

    if (tid == 0) sm.gen0 = ldcg_u32(&g_gen); // snapshot before any arrival
    __syncthreads();
    const unsigned gen0 = sm.gen0;

    const int i    = bid >> 6;                // MLP instance 0/1
    const int row0 = (bid & 63) * 4;

    // ================= P1: edge scatter (blocks 0-7) + p_i MLPs ============
    if (bid < 8) {
        // dtype sniff: int64 node ids (<256, nonneg) => odd int32 words zero
        int probe = (2 * tid + 1 < 2 * E) ? ei32[2 * tid + 1] : 0;
        int is64 = __syncthreads_and(probe == 0);
        for (int e = bid * NT + tid; e < E; e += 8 * NT) {
            int a, b;
            if (is64) { a = ei32[2 * e]; b = ei32[2 * (E + e)]; }
            else      { a = ei32[e];     b = ei32[E + e]; }
            a &= 255; b &= 255;
            atomicOr(&g_adj[a * 8 + (b >> 5)], 1u << (b & 31));
            atomicOr(&g_adj[b * 8 + (a >> 5)], 1u << (a & 31));
        }
    }
    // load 4 rows of x into smem
    if (tid < 128) {
        int rr = tid >> 5, ln = tid & 31;
        ((float4*)sm.u.p1.X[rr])[ln] = x4[(row0 + rr) * 32 + ln];
    }
    __syncthreads();
    {   // layer 1: h = relu(x * (w1[0,i][:128]+w1[0,i][128:]) + b1[0,i])
        const float2* W1 = (const float2*)w1 + (size_t)i * 256 * 64;  // w1[0,i]
        float2 acc = {0.f, 0.f};
#pragma unroll 8
        for (int k = 0; k < DD; k++) {
            float xk = sm.u.p1.X[r][k];
            float2 wa = W1[k * 64 + (c0 >> 1)];
            float2 wb = W1[(k + 128) * 64 + (c0 >> 1)];
            acc.x = fmaf(xk, wa.x + wb.x, acc.x);
            acc.y = fmaf(xk, wa.y + wb.y, acc.y);
        }
        float2 hv;
        hv.x = fmaxf(acc.x + b1[i * DD + c0],     0.f);
        hv.y = fmaxf(acc.y + b1[i * DD + c0 + 1], 0.f);
        ((float2*)sm.u.p1.H[r])[c0 >> 1] = hv;
    }
    __syncthreads();
    {   // layer 2: p_i = h * w2[0,i] + b2[0,i]
        const float2* W2 = (const float2*)w2 + (size_t)i * 128 * 64;  // w2[0,i]
        float2 acc = {0.f, 0.f};
#pragma unroll 8
        for (int k = 0; k < DD; k++) {
            float hk = sm.u.p1.H[r][k];
            float2 wv = W2[k * 64 + (c0 >> 1)];
            acc.x = fmaf(hk, wv.x, acc.x);
            acc.y = fmaf(hk, wv.y, acc.y);
        }
        float2 pv;
        pv.x = acc.x + b2[i * DD + c0];
        pv.y = acc.y + b2[i * DD + c0 + 1];
        float* dst = i ? g_p1 : g_p0;
        ((float2*)(dst + (row0 + r) * DD + c0))[0] = pv;
    }
    // build W1e[1][*] for P2: 8192 float4 spread over 128 blocks (64 each)
    {
        const float4* w14 = (const float4*)w1;
        if (tid < 64) {
            int j  = bid * 64 + tid;          // [0, 8192): two 4096-f4 matrices
            int ii = j >> 12, rem = j & 4095;
            ((float4*)g_W1e)[j] = f4add(w14[(2 + ii) * 8192 + rem],
                                        w14[(2 + ii) * 8192 + rem + 4096]);
        }
    }
    grid_sync(gen0 + 1);

    // ====== P2: u = x + gather(p0), d = p1-p0; Un_i/Dt_i = {u,d}*W1e[1,i] ===
    int myCnt = 0;
    if (w < 4) {                              // warps 0-3: neighbor lists
        int row = row0 + w;
        myCnt = build_list(row, sm.nbr[w]);
        if (lane == 0) {
            sm.cnts[w]  = myCnt;
            sm.selfS[w] = (g_adj[row * 8 + (row >> 5)] >> (row & 31)) & 1;
        }
    } else {                                  // warps 4-7: d = p1 - p0
        int row = row0 + (w - 4);
        float4 p1v = ((const float4*)g_p1)[row * 32 + lane];
        float4 p0v = ((const float4*)g_p0)[row * 32 + lane];
        float4 dv = make_float4(p1v.x - p0v.x, p1v.y - p0v.y,
                                p1v.z - p0v.z, p1v.w - p0v.w);
        ((float4*)sm.u.p2.D[w - 4])[lane] = dv;
        if (i == 0) ((float4*)g_d)[row * 32 + lane] = dv;
    }
    __syncthreads();
    if (w < 4) {                              // warps 0-3: gather u
        int row = row0 + w;
        const float4* p04 = (const float4*)g_p0;
        float4 a0 = x4[row * 32 + lane];
        float4 a1 = {}, a2 = {}, a3 = {};
        int j = 0;
        for (; j + 4 <= myCnt; j += 4) {
            a0 = f4add(a0, p04[sm.nbr[w][j]     * 32 + lane]);
            a1 = f4add(a1, p04[sm.nbr[w][j + 1] * 32 + lane]);
            a2 = f4add(a2, p04[sm.nbr[w][j + 2] * 32 + lane]);
            a3 = f4add(a3, p04[sm.nbr[w][j + 3] * 32 + lane]);
        }
        for (; j < myCnt; j++) a0 = f4add(a0, p04[sm.nbr[w][j] * 32 + lane]);
        float4 uv = f4add(f4add(a0, a1), f4add(a2, a3));
        ((float4*)sm.u.p2.U[w])[lane] = uv;
        if (i == 0) ((float4*)g_u)[row * 32 + lane] = uv;
    }
    __syncthreads();
    {   // matvec: Un_i[row][c0..], Dt_i[row][c0..]
        const float2* W = (const float2*)(g_W1e + i * DD * DD);
        float2 aU = {0.f, 0.f}, aD = {0.f, 0.f};
#pragma unroll 8
        for (int k = 0; k < DD; k++) {
            float uk = sm.u.p2.U[r][k];
            float dk = sm.u.p2.D[r][k];
            float2 wv = W[k * 64 + (c0 >> 1)];
            aU.x = fmaf(uk, wv.x, aU.x);  aU.y = fmaf(uk, wv.y, aU.y);
            aD.x = fmaf(dk, wv.x, aD.x);  aD.y = fmaf(dk, wv.y, aD.y);
        }
        ((float2*)&g_UD[2 * i    ][(row0 + r) * DD + c0])[0] = aU;
        ((float2*)&g_UD[2 * i + 1][(row0 + r) * DD + c0])[0] = aD;
    }
    grid_sync(gen0 + 2);
    if (bid >= 64) return;                    // lists for rows bid*4 live in blocks <64

    // ===== P3: S_t relu-gather + final matvec + self fix + out =============
    {
        int row = row0 + r;                   // same rows as this block's P2 (i==0)
        const float4* UD0 = (const float4*)g_UD[0];
        float4 pre = f4add(((const float4*)g_UD[1])[row * 32 + lane],
                           ((const float4*)(b1 + 2 * DD))[lane]);
        int n = sm.cnts[r];
        float4 s0 = {}, s1 = {};
        int j = h;                            // warp-half splits neighbors mod 2
        for (; j + 2 < n; j += 4) {
            s0 = f4add(s0, f4relu(f4add(UD0[sm.nbr[r][j]     * 32 + lane], pre)));
            s1 = f4add(s1, f4relu(f4add(UD0[sm.nbr[r][j + 2] * 32 + lane], pre)));
        }
        if (j < n) s0 = f4add(s0, f4relu(f4add(UD0[sm.nbr[r][j] * 32 + lane], pre)));
        ((float4*)sm.u.p3.Sp[r][h])[lane] = f4add(s0, s1);
    }
    __syncthreads();
    {   // final matvec: A2[row][c0..] = Ssum[row] . w2[1,0][:,c0..]
        const float2* W20 = (const float2*)w2 + 16384;      // w2[1,0]
        float2 acc = {0.f, 0.f};
#pragma unroll 8
        for (int k = 0; k < DD; k++) {
            float s = sm.u.p3.Sp[r][0][k] + sm.u.p3.Sp[r][1][k];
            float2 wv = W20[k * 64 + (c0 >> 1)];
            acc.x = fmaf(s, wv.x, acc.x);
            acc.y = fmaf(s, wv.y, acc.y);
        }
        ((float2*)&sm.u.p3.A2[r][c0])[0] = acc;
    }
    __syncthreads();
    {   // epilogue (all threads; tid>=128 duplicates compute, stores masked)
        int c = tid & 127, dup = tid >> 7;
        float b20 = b2[2 * DD + c];
        float b10 = b1[2 * DD + c];
#pragma unroll
        for (int rr = 0; rr < 4; rr++) {
            int row = row0 + rr;
            float sf = (float)sm.selfS[rr];
            float res = g_u[row * DD + c] + sf * g_d[row * DD + c]
                      + sm.u.p3.A2[rr][c] + (float)sm.cnts[rr] * b20;
            if (sm.selfS[rr]) {               // block-uniform, rare (~8/256 rows)
                if (dup == 0) {
                    sm.u.p3.Hs[0][c] = fmaxf(g_UD[0][row * DD + c]
                                            + g_UD[1][row * DD + c] + b10, 0.f);
                    sm.u.p3.Hs[1][c] = fmaxf(g_UD[2][row * DD + c]
                                            + g_UD[3][row * DD + c] + b1[3 * DD + c], 0.f);
                }
                __syncthreads();
                const float* W20f = w2 + 32768;   // w2[1,0]
                const float* W21f = w2 + 49152;   // w2[1,1]
                float d0 = 0.f, d1 = 0.f;
#pragma unroll 4
                for (int k = 0; k < DD; k++) {
                    d0 = fmaf(sm.u.p3.Hs[0][k], W20f[k * DD + c], d0);
                    d1 = fmaf(sm.u.p3.Hs[1][k], W21f[k * DD + c], d1);
                }
                res += (d1 + b2[3 * DD + c]) - (d0 + b20);
                __syncthreads();
            }
            if (dup == 0) out[row * DD + c] = res;
        }
    }
    // restore adjacency rows row0..row0+3 for the next graph replay
    __syncthreads();
    if (tid < 32) g_adj[bid * 32 + tid] = 0u;
}

extern "C" void kernel_launch(void* const* d_in, const int* in_sizes, int n_in,
                              void* d_out, int out_size) {
    const float* x  = (const float*)d_in[0];
    const float* w1 = (const float*)d_in[1];
    const float* b1 = (const float*)d_in[2];
    const float* w2 = (const float*)d_in[3];
    const float* b2 = (const float*)d_in[4];
    const int*   ei = (const int*)d_in[5];   // dtype sniffed on device
    int E = in_sizes[5] / 2;
    float* out = (float*)d_out;

    k_fused<<<NB, NT>>>(ei, E, (const float4*)x, w1, b1, w2, b2, out);
}

// round 8
// speedup vs baseline: 1.1488x; 1.1488x over previous
#include <cuda_runtime.h>

// IDGNN restructured (math validated R2-R7, rel_err ~2e-7):
//   p_i = MLP_{0,i}(x);  u = x + A*p0;  d = p1 - p0
//   Un_i = u*W1e[1,i]; Dt_i = d*W1e[1,i]   (W1e[k] = w1[k]+w1[k+128])
//   S_t = sum_{n in N(t)} relu(Un0[n] + Dt0[t] + b1[1,0])
//   out[t] = u_t + self_t*d_t + S_t*w2[1,0] + deg_t*b2[1,0]
//            + self_t*( (relu(Un1_t+Dt1_t+b1[1,1])*w2[1,1]+b2[1,1])
//                      -(relu(Un0_t+Dt0_t+b1[1,0])*w2[1,0]+b2[1,0]) )
// R8: split-K GEMM layout everywhere (warp=(row,k-slice), lane=4 cols f4),
// hierarchical grid barrier (16 leaves + root), layer-0 via K=256 k&127 view,
// layer-1 weights folded once. 128 blocks x 256 threads, single launch.

#define NN 256
#define DD 128
#define NB 128
#define NT 256

// ---- device scratch (zero-init at load; g_adj restored each call) ----
__device__ unsigned g_adj[NN * 8];
__device__ __align__(16) float g_W1e[2 * DD * DD];   // folded w1[1,i]
__device__ __align__(16) float g_p0[NN * DD];
__device__ __align__(16) float g_p1[NN * DD];
__device__ __align__(16) float g_u [NN * DD];
__device__ __align__(16) float g_d [NN * DD];
__device__ __align__(16) float g_UD[4][NN * DD];     // 0:Un0 1:Dt0 2:Un1 3:Dt1
__device__ unsigned g_leaf[16 * 64];   // 256B stride -> distinct L2 slices
__device__ unsigned g_root;
__device__ unsigned g_gen;

__device__ __forceinline__ float4 f4add(float4 a, float4 b) {
    return make_float4(a.x + b.x, a.y + b.y, a.z + b.z, a.w + b.w);
}
__device__ __forceinline__ float4 f4fma(float s, float4 w, float4 a) {
    return make_float4(fmaf(s, w.x, a.x), fmaf(s, w.y, a.y),
                       fmaf(s, w.z, a.z), fmaf(s, w.w, a.w));
}
__device__ __forceinline__ float4 f4relu(float4 a) {
    return make_float4(fmaxf(a.x, 0.f), fmaxf(a.y, 0.f),
                       fmaxf(a.z, 0.f), fmaxf(a.w, 0.f));
}
__device__ __forceinline__ unsigned ldcg_u32(const unsigned* p) {
    unsigned v;
    asm volatile("ld.global.cg.u32 %0, [%1];" : "=r"(v) : "l"(p));
    return v;
}

// Hierarchical grid barrier: 8 arrivals per leaf (16 leaves, distinct L2
// slices), leaf finishers arrive at root, root finisher publishes target.
// Pollers use plain L2 loads. Counters self-reset; g_gen monotonic.
__device__ __forceinline__ void grid_sync(unsigned target, int bid) {
    __syncthreads();
    if (threadIdx.x == 0) {
        __threadfence();
        unsigned* leaf = &g_leaf[(bid & 15) * 64];
        unsigned a = atomicAdd(leaf, 1u);
        if (a == 7u) {
            atomicExch(leaf, 0u);
            unsigned rr = atomicAdd(&g_root, 1u);
            if (rr == 15u) {
                atomicExch(&g_root, 0u);
                __threadfence();
                atomicExch(&g_gen, target);
            }
        }
        while (ldcg_u32(&g_gen) != target) __nanosleep(32);
        __threadfence();
    }
    __syncthreads();
}

// Expand g_adj[row] bitmask into nbr[] (full warp). Returns count.
__device__ __forceinline__ int build_list(int row, int* nbr) {
    int lane = threadIdx.x & 31;
    unsigned word = (lane < 8) ? g_adj[row * 8 + lane] : 0u;
    int pc = __popc(word);
    int inc = pc;
#pragma unroll
    for (int off = 1; off < 8; off <<= 1) {
        int v = __shfl_up_sync(0xffffffffu, inc, off);
        if (lane >= off) inc += v;
    }
    int base = inc - pc;
    if (lane < 8) {
        unsigned bits = word; int o = base;
        while (bits) { int b = __ffs(bits) - 1; bits &= bits - 1; nbr[o++] = lane * 32 + b; }
    }
    return __shfl_sync(0xffffffffu, inc, 7);
}

struct Smem {
    int nbr[4][NN];            // persists P2 -> P3
    int cnts[4];
    int selfS[4];
    unsigned gen0;
    __align__(16) union {      // 16B-aligned: float4 LDS/STS inside
        struct { float X[4][DD]; float part[2][4][DD]; float H[4][DD]; } p1;   // 8 KB
        struct { float U[4][DD]; float D[4][DD];
                 float pA[2][4][DD]; float pB[2][4][DD]; } p2;                 // 12 KB
        struct { float Ssum[2][DD]; float pS[4][2][DD];
                 float pA[4][2][DD]; float Hs[2][DD]; } p3;                    // 10 KB
    } u;
};

__global__ void __launch_bounds__(NT, 1)
k_fused(const int* __restrict__ ei32, int E,
        const float4* __restrict__ x4, const float4* __restrict__ w14,
        const float* __restrict__ b1, const float4* __restrict__ w24,
        const float* __restrict__ b2, float* __restrict__ out) {
    __shared__ Smem sm;
    const int tid = threadIdx.x, lane = tid & 31, w = tid >> 5, bid = blockIdx.x;
    const int i    = bid >> 6;               // MLP instance 0/1
    const int row0 = (bid & 63) * 4;
    const float* xf = (const float*)x4;
    const float* w2f = (const float*)w24;
    const float4* W1e4 = (const float4*)g_W1e;

    if (tid == 0) sm.gen0 = ldcg_u32(&g_gen);
    __syncthreads();
    const unsigned gen0 = sm.gen0;

    // ===== P1 setup: edge scatter (blocks 0-7), X load, W1e fold ==========
    if (bid < 8) {
        // dtype sniff: int64 node ids (<256, nonneg) => odd int32 words zero
        int probe = (2 * tid + 1 < 2 * E) ? ei32[2 * tid + 1] : 0;
        int is64 = __syncthreads_and(probe == 0);
        for (int e = bid * NT + tid; e < E; e += 8 * NT) {
            int a, b;
            if (is64) { a = ei32[2 * e]; b = ei32[2 * (E + e)]; }
            else      { a = ei32[e];     b = ei32[E + e]; }
            a &= 255; b &= 255;
            atomicOr(&g_adj[a * 8 + (b >> 5)], 1u << (b & 31));
            atomicOr(&g_adj[b * 8 + (a >> 5)], 1u << (a & 31));
        }
    }
    if (tid < 128) {
        int rr = tid >> 5, ln = tid & 31;
        ((float4*)sm.u.p1.X[rr])[ln] = x4[(row0 + rr) * 32 + ln];
    }
    {   // fold layer-1 weights: 8192 f4 spread over 128 blocks
        if (tid < 64) {
            int j  = bid * 64 + tid;
            int ii = j >> 12, rem = j & 4095;
            ((float4*)g_W1e)[j] = f4add(w14[(2 + ii) * 8192 + rem],
                                        w14[(2 + ii) * 8192 + rem + 4096]);
        }
    }
    __syncthreads();

    // ===== P1a: layer-0 L1 GEMM, K=256 view (X[k&127]) ======================
    {
        const int r = w & 3, q = w >> 2;     // row-in-block, k-half of 256
        float4 acc = {};
#pragma unroll 8
        for (int kk = 0; kk < 128; kk++) {
            int k = q * 128 + kk;
            float4 wv = w14[i * 8192 + k * 32 + lane];   // w1[0,i][k][4*lane..]
            acc = f4fma(sm.u.p1.X[r][k & 127], wv, acc);
        }
        ((float4*)sm.u.p1.part[q][r])[lane] = acc;
    }
    __syncthreads();
#pragma unroll
    for (int v = 0; v < 2; v++) {            // H = relu(part0+part1+b1[0,i])
        int idx = tid + 256 * v, r = idx >> 7, c = idx & 127;
        sm.u.p1.H[r][c] = fmaxf(sm.u.p1.part[0][r][c] + sm.u.p1.part[1][r][c]
                                + b1[i * DD + c], 0.f);
    }
    __syncthreads();
    // ===== P1b: layer-0 L2 GEMM, K=128 ======================================
    {
        const int r = w & 3, q = w >> 2;     // k-half of 128
        float4 acc = {};
#pragma unroll 8
        for (int kk = 0; kk < 64; kk++) {
            int k = q * 64 + kk;
            float4 wv = w24[i * 4096 + k * 32 + lane];   // w2[0,i]
            acc = f4fma(sm.u.p1.H[r][k], wv, acc);
        }
        ((float4*)sm.u.p1.part[q][r])[lane] = acc;
    }
    __syncthreads();
    {
        float* dst = i ? g_p1 : g_p0;
#pragma unroll
        for (int v = 0; v < 2; v++) {
            int idx = tid + 256 * v, r = idx >> 7, c = idx & 127;
            dst[(row0 + r) * DD + c] = sm.u.p1.part[0][r][c]
                                     + sm.u.p1.part[1][r][c] + b2[i * DD + c];
        }
    }
    grid_sync(gen0 + 1, bid);

    // ===== P2: lists, d, u-gather, then {u,d} x W1e[1,i] GEMM ===============
    if (w < 4) {                             // warps 0-3: neighbor lists
        int row = row0 + w;
        int cn = build_list(row, sm.nbr[w]);
        if (lane == 0) {
            sm.cnts[w]  = cn;
            sm.selfS[w] = (g_adj[row * 8 + (row >> 5)] >> (row & 31)) & 1;
        }
    } else {                                 // warps 4-7: d = p1 - p0
        int row = row0 + (w - 4);
        float4 p1v = ((const float4*)g_p1)[row * 32 + lane];
        float4 p0v = ((const float4*)g_p0)[row * 32 + lane];
        float4 dv = make_float4(p1v.x - p0v.x, p1v.y - p0v.y,
                                p1v.z - p0v.z, p1v.w - p0v.w);
        ((float4*)sm.u.p2.D[w - 4])[lane] = dv;
        if (i == 0) ((float4*)g_d)[row * 32 + lane] = dv;
    }
    __syncthreads();
    {   // u-gather: warp (r, half) splits the list mod 2
        const int r = w & 3, half = w >> 2;
        const float4* p04 = (const float4*)g_p0;
        int cn = sm.cnts[r];
        float4 s0 = {}, s1 = {};
        int j = half;
        for (; j + 2 < cn; j += 4) {
            s0 = f4add(s0, p04[sm.nbr[r][j]     * 32 + lane]);
            s1 = f4add(s1, p04[sm.nbr[r][j + 2] * 32 + lane]);
        }
        if (j < cn) s0 = f4add(s0, p04[sm.nbr[r][j] * 32 + lane]);
        ((float4*)sm.u.p2.pA[half][r])[lane] = f4add(s0, s1);
    }
    __syncthreads();
#pragma unroll
    for (int v = 0; v < 2; v++) {            // U = x + partials; store g_u
        int idx = tid + 256 * v, r = idx >> 7, c = idx & 127;
        float uv = xf[(row0 + r) * DD + c]
                 + sm.u.p2.pA[0][r][c] + sm.u.p2.pA[1][r][c];
        sm.u.p2.U[r][c] = uv;
        if (i == 0) g_u[(row0 + r) * DD + c] = uv;
    }
    __syncthreads();
    {   // GEMM: accU/accD share each weight load
        const int r = w & 3, q = w >> 2;
        float4 aU = {}, aD = {};
#pragma unroll 8
        for (int kk = 0; kk < 64; kk++) {
            int k = q * 64 + kk;
            float4 wv = W1e4[i * 4096 + k * 32 + lane];
            aU = f4fma(sm.u.p2.U[r][k], wv, aU);
            aD = f4fma(sm.u.p2.D[r][k], wv, aD);
        }
        ((float4*)sm.u.p2.pA[q][r])[lane] = aU;
        ((float4*)sm.u.p2.pB[q][r])[lane] = aD;
    }
    __syncthreads();
#pragma unroll
    for (int v = 0; v < 4; v++) {            // write Un_i / Dt_i
        int idx = tid + 256 * v;             // [0,1024): sel | r | c
        int sel = idx >> 9, r = (idx >> 7) & 3, c = idx & 127;
        float s = sel ? (sm.u.p2.pB[0][r][c] + sm.u.p2.pB[1][r][c])
                      : (sm.u.p2.pA[0][r][c] + sm.u.p2.pA[1][r][c]);
        g_UD[2 * i + sel][(row0 + r) * DD + c] = s;
    }
    grid_sync(gen0 + 2, bid);

    // ===== P3: 2 rows per block (i picks pair); lists persist in smem ======
    {
        // relu-gather: warp (rl, g) splits list mod 4
        const int rl = w & 1, g = w >> 1;
        const int lr = 2 * i + rl, row = row0 + lr;
        const float4* UD0 = (const float4*)g_UD[0];
        float4 pre = f4add(((const float4*)g_UD[1])[row * 32 + lane],
                           ((const float4*)(b1 + 2 * DD))[lane]);
        int cn = sm.cnts[lr];
        float4 s0 = {}, s1 = {};
        int j = g;
        for (; j + 4 < cn; j += 8) {
            s0 = f4add(s0, f4relu(f4add(UD0[sm.nbr[lr][j]     * 32 + lane], pre)));
            s1 = f4add(s1, f4relu(f4add(UD0[sm.nbr[lr][j + 4] * 32 + lane], pre)));
        }
        if (j < cn) s0 = f4add(s0, f4relu(f4add(UD0[sm.nbr[lr][j] * 32 + lane], pre)));
        ((float4*)sm.u.p3.pS[g][rl])[lane] = f4add(s0, s1);
    }
    __syncthreads();
    {   // Ssum reduce: 256 vals / 256 threads
        int rl = tid >> 7, c = tid & 127;
        sm.u.p3.Ssum[rl][c] = sm.u.p3.pS[0][rl][c] + sm.u.p3.pS[1][rl][c]
                            + sm.u.p3.pS[2][rl][c] + sm.u.p3.pS[3][rl][c];
    }
    __syncthreads();
    {   // final GEMM: warp (rl, k-quarter), K=128
        const int rl = w & 1, q = w >> 1;
        float4 acc = {};
#pragma unroll 8
        for (int kk = 0; kk < 32; kk++) {
            int k = q * 32 + kk;
            float4 wv = w24[8192 + k * 32 + lane];       // w2[1,0]
            acc = f4fma(sm.u.p3.Ssum[rl][k], wv, acc);
        }
        ((float4*)sm.u.p3.pA[q][rl])[lane] = acc;
    }
    __syncthreads();
    {   // epilogue
        const int rl = tid >> 7, c = tid & 127;
        const int lr = 2 * i + rl, row = row0 + lr;
        float a2 = sm.u.p3.pA[0][rl][c] + sm.u.p3.pA[1][rl][c]
                 + sm.u.p3.pA[2][rl][c] + sm.u.p3.pA[3][rl][c];
        float sf = (float)sm.selfS[lr];
        float res = g_u[row * DD + c] + sf * g_d[row * DD + c]
                  + a2 + (float)sm.cnts[lr] * b2[2 * DD + c];
#pragma unroll
        for (int rr = 0; rr < 2; rr++) {
            if (sm.selfS[2 * i + rr]) {      // block-uniform, rare
                int rowx = row0 + 2 * i + rr;
                if (tid < 128) {
                    sm.u.p3.Hs[0][tid] = fmaxf(g_UD[0][rowx * DD + tid]
                                              + g_UD[1][rowx * DD + tid]
                                              + b1[2 * DD + tid], 0.f);
                    sm.u.p3.Hs[1][tid] = fmaxf(g_UD[2][rowx * DD + tid]
                                              + g_UD[3][rowx * DD + tid]
                                              + b1[3 * DD + tid], 0.f);
                }
                __syncthreads();
                float d0 = 0.f, d1 = 0.f;
#pragma unroll 4
                for (int k = 0; k < DD; k++) {
                    d0 = fmaf(sm.u.p3.Hs[0][k], w2f[32768 + k * DD + c], d0);
                    d1 = fmaf(sm.u.p3.Hs[1][k], w2f[49152 + k * DD + c], d1);
                }
                if (rl == rr)
                    res += (d1 + b2[3 * DD + c]) - (d0 + b2[2 * DD + c]);
                __syncthreads();
            }
        }
        out[row * DD + c] = res;
    }
    // restore adjacency rows for the next graph replay (dup writes are fine)
    __syncthreads();
    if (tid < 32) g_adj[row0 * 8 + tid] = 0u;
}

extern "C" void kernel_launch(void* const* d_in, const int* in_sizes, int n_in,
                              void* d_out, int out_size) {
    const float* x  = (const float*)d_in[0];
    const float* w1 = (const float*)d_in[1];
    const float* b1 = (const float*)d_in[2];
    const float* w2 = (const float*)d_in[3];
    const float* b2 = (const float*)d_in[4];
    const int*   ei = (const int*)d_in[5];   // dtype sniffed on device
    int E = in_sizes[5] / 2;
    float* out = (float*)d_out;

    k_fused<<<NB, NT>>>(ei, E, (const float4*)x, (const float4*)w1,
                        b1, (const float4*)w2, b2, out);
}

// round 9
// speedup vs baseline: 1.3900x; 1.2100x over previous
#include <cuda_runtime.h>

// IDGNN restructured (math validated R2-R8, rel_err ~2e-7):
//   p_i = MLP_{0,i}(x);  u = x + A*p0;  d = p1 - p0
//   Un_i = u*W1e[1,i]; Dt_i = d*W1e[1,i]   (W1e[k] = w1[k]+w1[k+128], inline fold)
//   S_t = sum_{n in N(t)} relu(Un0[n] + Dt0[t] + b1[1,0])
//   out[t] = u_t + self_t*d_t + S_t*w2[1,0] + deg_t*b2[1,0]
//            + self_t*( (relu(Un1_t+Dt1_t+b1[1,1])*w2[1,1]+b2[1,1])
//                      -(relu(Un0_t+Dt0_t+b1[1,0])*w2[1,0]+b2[1,0]) )
// R9: fused, 128x256, 2 hierarchical grid barriers, weight-shared GEMMs
// (warp=k-slice, 4 rows per weight load, inline w1 fold), lists persist P2->P3.

#define NN 256
#define DD 128
#define NB 128
#define NT 256

__device__ unsigned g_adj[NN * 8];
__device__ __align__(16) float g_p0[NN * DD];
__device__ __align__(16) float g_p1[NN * DD];
__device__ __align__(16) float g_u [NN * DD];
__device__ __align__(16) float g_d [NN * DD];
__device__ __align__(16) float g_UD[4][NN * DD];     // 0:Un0 1:Dt0 2:Un1 3:Dt1
__device__ unsigned g_leaf[16 * 64];   // 256B stride -> distinct L2 slices
__device__ unsigned g_root;
__device__ unsigned g_gen;

__device__ __forceinline__ float4 f4add(float4 a, float4 b) {
    return make_float4(a.x + b.x, a.y + b.y, a.z + b.z, a.w + b.w);
}
__device__ __forceinline__ float4 f4fma(float s, float4 w, float4 a) {
    return make_float4(fmaf(s, w.x, a.x), fmaf(s, w.y, a.y),
                       fmaf(s, w.z, a.z), fmaf(s, w.w, a.w));
}
__device__ __forceinline__ float4 f4relu(float4 a) {
    return make_float4(fmaxf(a.x, 0.f), fmaxf(a.y, 0.f),
                       fmaxf(a.z, 0.f), fmaxf(a.w, 0.f));
}
__device__ __forceinline__ unsigned ldcg_u32(const unsigned* p) {
    unsigned v;
    asm volatile("ld.global.cg.u32 %0, [%1];" : "=r"(v) : "l"(p));
    return v;
}

// Hierarchical grid barrier: 16 leaves x 8 arrivals, then 16-arrival root.
// Poll is a plain L2 load. Counters self-reset; g_gen monotonic across replays.
__device__ __forceinline__ void grid_sync(unsigned target, int bid) {
    __syncthreads();
    if (threadIdx.x == 0) {
        __threadfence();
        unsigned* leaf = &g_leaf[(bid & 15) * 64];
        unsigned a = atomicAdd(leaf, 1u);
        if (a == 7u) {
            atomicExch(leaf, 0u);
            unsigned rr = atomicAdd(&g_root, 1u);
            if (rr == 15u) {
                atomicExch(&g_root, 0u);
                __threadfence();
                atomicExch(&g_gen, target);
            }
        }
        while (ldcg_u32(&g_gen) != target) __nanosleep(32);
        __threadfence();
    }
    __syncthreads();
}

// Expand g_adj[row] bitmask into nbr[] (full warp). Returns count.
__device__ __forceinline__ int build_list(int row, int* nbr) {
    int lane = threadIdx.x & 31;
    unsigned word = (lane < 8) ? g_adj[row * 8 + lane] : 0u;
    int pc = __popc(word);
    int inc = pc;
#pragma unroll
    for (int off = 1; off < 8; off <<= 1) {
        int v = __shfl_up_sync(0xffffffffu, inc, off);
        if (lane >= off) inc += v;
    }
    int base = inc - pc;
    if (lane < 8) {
        unsigned bits = word; int o = base;
        while (bits) { int b = __ffs(bits) - 1; bits &= bits - 1; nbr[o++] = lane * 32 + b; }
    }
    return __shfl_sync(0xffffffffu, inc, 7);
}

struct Smem {
    int nbr[4][NN];            // persists P2 -> P3 (bid<64 reuse their rows)
    int cnts[4];
    int selfS[4];
    unsigned gen0;
    __align__(16) union {
        struct { float X[4][DD]; float H[4][DD]; float part[8][4][DD]; } p1; // 20KB
        struct { float U[4][DD]; float D[4][DD];
                 float pU[8][4][DD]; float pD[8][4][DD]; } p2;               // 36KB
        struct { float Ssum[4][DD]; float pS[2][4][DD];
                 float pA[8][4][DD]; float Hs[2][DD]; } p3;                  // 23KB
    } u;
};

__global__ void __launch_bounds__(NT, 1)
k_fused(const int* __restrict__ ei32, int E,
        const float* __restrict__ xf, const float4* __restrict__ w14,
        const float* __restrict__ b1, const float4* __restrict__ w24,
        const float* __restrict__ b2, float* __restrict__ out) {
    __shared__ Smem sm;
    const int tid = threadIdx.x, lane = tid & 31, w = tid >> 5, bid = blockIdx.x;
    const int i    = bid >> 6;                // MLP instance 0/1
    const int row0 = (bid & 63) * 4;
    const int kb   = w * 16;                  // this warp's k-slice
    const float4* x4 = (const float4*)xf;
    const float* w2f = (const float*)w24;

    if (tid == 0) sm.gen0 = ldcg_u32(&g_gen);
    __syncthreads();
    const unsigned gen0 = sm.gen0;

    // ===== P1: edge scatter (blocks 0-7) + p_i = MLP_{0,i}(x) ==============
    if (bid < 8) {
        // dtype sniff: int64 node ids (<256, nonneg) => odd int32 words zero
        int probe = (2 * tid + 1 < 2 * E) ? ei32[2 * tid + 1] : 0;
        int is64 = __syncthreads_and(probe == 0);
        for (int e = bid * NT + tid; e < E; e += 8 * NT) {
            int a, b;
            if (is64) { a = ei32[2 * e]; b = ei32[2 * (E + e)]; }
            else      { a = ei32[e];     b = ei32[E + e]; }
            a &= 255; b &= 255;
            atomicOr(&g_adj[a * 8 + (b >> 5)], 1u << (b & 31));
            atomicOr(&g_adj[b * 8 + (a >> 5)], 1u << (a & 31));
        }
    }
    if (tid < 128) {
        int rr = tid >> 5, ln = tid & 31;
        ((float4*)sm.u.p1.X[rr])[ln] = x4[(row0 + rr) * 32 + ln];
    }
    __syncthreads();
    {   // L1 GEMM with inline fold: each weight pair feeds 4 rows
        float4 acc[4] = {};
#pragma unroll
        for (int kk = 0; kk < 16; kk++) {
            int k = kb + kk;
            float4 wa = w14[i * 8192 + k * 32 + lane];
            float4 wb = w14[i * 8192 + (k + 128) * 32 + lane];
            float4 we = f4add(wa, wb);
#pragma unroll
            for (int r = 0; r < 4; r++) acc[r] = f4fma(sm.u.p1.X[r][k], we, acc[r]);
        }
#pragma unroll
        for (int r = 0; r < 4; r++) ((float4*)sm.u.p1.part[w][r])[lane] = acc[r];
    }
    __syncthreads();
#pragma unroll
    for (int v = 0; v < 2; v++) {             // H = relu(sum parts + b1[0,i])
        int idx = tid + 256 * v, r = idx >> 7, c = idx & 127;
        float s = b1[i * DD + c];
#pragma unroll
        for (int ww = 0; ww < 8; ww++) s += sm.u.p1.part[ww][r][c];
        sm.u.p1.H[r][c] = fmaxf(s, 0.f);
    }
    __syncthreads();
    {   // L2 GEMM
        float4 acc[4] = {};
#pragma unroll
        for (int kk = 0; kk < 16; kk++) {
            int k = kb + kk;
            float4 wv = w24[i * 4096 + k * 32 + lane];
#pragma unroll
            for (int r = 0; r < 4; r++) acc[r] = f4fma(sm.u.p1.H[r][k], wv, acc[r]);
        }
#pragma unroll
        for (int r = 0; r < 4; r++) ((float4*)sm.u.p1.part[w][r])[lane] = acc[r];
    }
    __syncthreads();
    {
        float* dst = i ? g_p1 : g_p0;
#pragma unroll
        for (int v = 0; v < 2; v++) {
            int idx = tid + 256 * v, r = idx >> 7, c = idx & 127;
            float s = b2[i * DD + c];
#pragma unroll
            for (int ww = 0; ww < 8; ww++) s += sm.u.p1.part[ww][r][c];
            dst[(row0 + r) * DD + c] = s;
        }
    }
    grid_sync(gen0 + 1, bid);

    // ===== P2: lists, d, u-gather, {u,d} x W1e[1,i] GEMM (inline fold) =====
    if (w < 4) {
        int row = row0 + w;
        int cn = build_list(row, sm.nbr[w]);
        if (lane == 0) {
            sm.cnts[w]  = cn;
            sm.selfS[w] = (g_adj[row * 8 + (row >> 5)] >> (row & 31)) & 1;
        }
    } else {
        int row = row0 + (w - 4);
        float4 p1v = ((const float4*)g_p1)[row * 32 + lane];
        float4 p0v = ((const float4*)g_p0)[row * 32 + lane];
        float4 dv = make_float4(p1v.x - p0v.x, p1v.y - p0v.y,
                                p1v.z - p0v.z, p1v.w - p0v.w);
        ((float4*)sm.u.p2.D[w - 4])[lane] = dv;
        if (i == 0) ((float4*)g_d)[row * 32 + lane] = dv;
    }
    __syncthreads();
    {   // u-gather: warp (r, half) splits list mod 2; partials into pU[0..1]
        const int r = w & 3, half = w >> 2;
        const float4* p04 = (const float4*)g_p0;
        int cn = sm.cnts[r];
        float4 s0 = {}, s1 = {};
        int j = half;
        for (; j + 2 < cn; j += 4) {
            s0 = f4add(s0, p04[sm.nbr[r][j]     * 32 + lane]);
            s1 = f4add(s1, p04[sm.nbr[r][j + 2] * 32 + lane]);
        }
        if (j < cn) s0 = f4add(s0, p04[sm.nbr[r][j] * 32 + lane]);
        ((float4*)sm.u.p2.pU[half][r])[lane] = f4add(s0, s1);
    }
    __syncthreads();
#pragma unroll
    for (int v = 0; v < 2; v++) {             // U = x + gathered partials
        int idx = tid + 256 * v, r = idx >> 7, c = idx & 127;
        float uv = xf[(row0 + r) * DD + c]
                 + sm.u.p2.pU[0][r][c] + sm.u.p2.pU[1][r][c];
        sm.u.p2.U[r][c] = uv;
        if (i == 0) g_u[(row0 + r) * DD + c] = uv;
    }
    __syncthreads();
    {   // GEMM: one folded weight pair feeds 8 FMAs x4 (U and D, 4 rows)
        float4 aU[4] = {}, aD[4] = {};
#pragma unroll
        for (int kk = 0; kk < 16; kk++) {
            int k = kb + kk;
            float4 wa = w14[(2 + i) * 8192 + k * 32 + lane];
            float4 wb = w14[(2 + i) * 8192 + (k + 128) * 32 + lane];
            float4 we = f4add(wa, wb);
#pragma unroll
            for (int r = 0; r < 4; r++) {
                aU[r] = f4fma(sm.u.p2.U[r][k], we, aU[r]);
                aD[r] = f4fma(sm.u.p2.D[r][k], we, aD[r]);
            }
        }
#pragma unroll
        for (int r = 0; r < 4; r++) {
            ((float4*)sm.u.p2.pU[w][r])[lane] = aU[r];
            ((float4*)sm.u.p2.pD[w][r])[lane] = aD[r];
        }
    }
    __syncthreads();
#pragma unroll
    for (int v = 0; v < 2; v++) {             // write Un_i / Dt_i
        int idx = tid + 256 * v, r = idx >> 7, c = idx & 127;
        float sU = 0.f, sD = 0.f;
#pragma unroll
        for (int ww = 0; ww < 8; ww++) {
            sU += sm.u.p2.pU[ww][r][c];
            sD += sm.u.p2.pD[ww][r][c];
        }
        g_UD[2 * i    ][(row0 + r) * DD + c] = sU;
        g_UD[2 * i + 1][(row0 + r) * DD + c] = sD;
    }
    grid_sync(gen0 + 2, bid);
    if (bid >= 64) return;                    // lists for these rows live here

    // ===== P3: relu-gather + final matvec + self fix + output ==============
    {
        const int r = w & 3, half = w >> 2;
        int row = row0 + r;
        const float4* UD0 = (const float4*)g_UD[0];
        float4 pre = f4add(((const float4*)g_UD[1])[row * 32 + lane],
                           ((const float4*)(b1 + 2 * DD))[lane]);
        int cn = sm.cnts[r];
        float4 s0 = {}, s1 = {};
        int j = half;
        for (; j + 2 < cn; j += 4) {
            s0 = f4add(s0, f4relu(f4add(UD0[sm.nbr[r][j]     * 32 + lane], pre)));
            s1 = f4add(s1, f4relu(f4add(UD0[sm.nbr[r][j + 2] * 32 + lane], pre)));
        }
        if (j < cn) s0 = f4add(s0, f4relu(f4add(UD0[sm.nbr[r][j] * 32 + lane], pre)));
        ((float4*)sm.u.p3.pS[half][r])[lane] = f4add(s0, s1);
    }
    __syncthreads();
#pragma unroll
    for (int v = 0; v < 2; v++) {
        int idx = tid + 256 * v, r = idx >> 7, c = idx & 127;
        sm.u.p3.Ssum[r][c] = sm.u.p3.pS[0][r][c] + sm.u.p3.pS[1][r][c];
    }
    __syncthreads();
    {   // final GEMM vs w2[1,0]
        float4 acc[4] = {};
#pragma unroll
        for (int kk = 0; kk < 16; kk++) {
            int k = kb + kk;
            float4 wv = w24[8192 + k * 32 + lane];
#pragma unroll
            for (int r = 0; r < 4; r++) acc[r] = f4fma(sm.u.p3.Ssum[r][k], wv, acc[r]);
        }
#pragma unroll
        for (int r = 0; r < 4; r++) ((float4*)sm.u.p3.pA[w][r])[lane] = acc[r];
    }
    __syncthreads();
    {   // epilogue: thread owns (r0, c) and (r0+2, c)
        const int r0 = tid >> 7, c = tid & 127;
        float res[2];
#pragma unroll
        for (int v = 0; v < 2; v++) {
            int rr = r0 + 2 * v, row = row0 + rr;
            float a2 = 0.f;
#pragma unroll
            for (int ww = 0; ww < 8; ww++) a2 += sm.u.p3.pA[ww][rr][c];
            float sf = (float)sm.selfS[rr];
            res[v] = g_u[row * DD + c] + sf * g_d[row * DD + c]
                   + a2 + (float)sm.cnts[rr] * b2[2 * DD + c];
        }
#pragma unroll
        for (int rr = 0; rr < 4; rr++) {
            if (sm.selfS[rr]) {               // block-uniform, rare (~8/256)
                int row = row0 + rr;
                if (tid < 128) {
                    sm.u.p3.Hs[0][tid] = fmaxf(g_UD[0][row * DD + tid]
                                              + g_UD[1][row * DD + tid]
                                              + b1[2 * DD + tid], 0.f);
                    sm.u.p3.Hs[1][tid] = fmaxf(g_UD[2][row * DD + tid]
                                              + g_UD[3][row * DD + tid]
                                              + b1[3 * DD + tid], 0.f);
                }
                __syncthreads();
                float d0 = 0.f, d1 = 0.f;
#pragma unroll 4
                for (int k = 0; k < DD; k++) {
                    d0 = fmaf(sm.u.p3.Hs[0][k], w2f[32768 + k * DD + c], d0);
                    d1 = fmaf(sm.u.p3.Hs[1][k], w2f[49152 + k * DD + c], d1);
                }
                float corr = (d1 + b2[3 * DD + c]) - (d0 + b2[2 * DD + c]);
                if (rr == r0)     res[0] += corr;
                if (rr == r0 + 2) res[1] += corr;
                __syncthreads();
            }
        }
        out[(row0 + r0) * DD + c]     = res[0];
        out[(row0 + r0 + 2) * DD + c] = res[1];
    }
    // restore adjacency rows for the next graph replay
    __syncthreads();
    if (tid < 32) g_adj[row0 * 8 + tid] = 0u;
}

extern "C" void kernel_launch(void* const* d_in, const int* in_sizes, int n_in,
                              void* d_out, int out_size) {
    const float* x  = (const float*)d_in[0];
    const float* w1 = (const float*)d_in[1];
    const float* b1 = (const float*)d_in[2];
    const float* w2 = (const float*)d_in[3];
    const float* b2 = (const float*)d_in[4];
    const int*   ei = (const int*)d_in[5];   // dtype sniffed on device
    int E = in_sizes[5] / 2;
    float* out = (float*)d_out;

    k_fused<<<NB, NT>>>(ei, E, x, (const float4*)w1, b1,
                        (const float4*)w2, b2, out);
}

// round 10
// speedup vs baseline: 1.4058x; 1.0114x over previous
#include <cuda_runtime.h>

// IDGNN restructured (math validated R2-R9, rel_err ~2e-7):
//   p_i = MLP_{0,i}(x);  u = x + A*p0;  d = p1 - p0
//   Un_i = u*W1e[1,i]; Dt_i = d*W1e[1,i]   (W1e[k] = w1[k]+w1[k+128], inline fold)
//   S_t = sum_{n in N(t)} relu(Un0[n] + Dt0[t] + b1[1,0])
//   out[t] = u_t + self_t*d_t + S_t*w2[1,0] + deg_t*b2[1,0]
//            + self_t*( (relu(Un1_t+Dt1_t+b1[1,1])*w2[1,1]+b2[1,1])
//                      -(relu(Un0_t+Dt0_t+b1[1,0])*w2[1,0]+b2[1,0]) )
// R10: 256 blocks x 256 threads, 2 blocks/SM co-resident (16 warps/SM) for
// latency hiding; 2 rows/block halves per-warp work. 2 hierarchical barriers.

#define NN 256
#define DD 128
#define NB 256
#define NT 256

__device__ unsigned g_adj[NN * 8];
__device__ __align__(16) float g_p0[NN * DD];
__device__ __align__(16) float g_p1[NN * DD];
__device__ __align__(16) float g_u [NN * DD];
__device__ __align__(16) float g_d [NN * DD];
__device__ __align__(16) float g_UD[4][NN * DD];     // 0:Un0 1:Dt0 2:Un1 3:Dt1
__device__ unsigned g_leaf[16 * 64];   // 256B stride -> distinct L2 slices
__device__ unsigned g_root;
__device__ unsigned g_gen;

__device__ __forceinline__ float4 f4add(float4 a, float4 b) {
    return make_float4(a.x + b.x, a.y + b.y, a.z + b.z, a.w + b.w);
}
__device__ __forceinline__ float4 f4fma(float s, float4 w, float4 a) {
    return make_float4(fmaf(s, w.x, a.x), fmaf(s, w.y, a.y),
                       fmaf(s, w.z, a.z), fmaf(s, w.w, a.w));
}
__device__ __forceinline__ float4 f4relu(float4 a) {
    return make_float4(fmaxf(a.x, 0.f), fmaxf(a.y, 0.f),
                       fmaxf(a.z, 0.f), fmaxf(a.w, 0.f));
}
__device__ __forceinline__ unsigned ldcg_u32(const unsigned* p) {
    unsigned v;
    asm volatile("ld.global.cg.u32 %0, [%1];" : "=r"(v) : "l"(p));
    return v;
}

// Hierarchical grid barrier: 16 leaves x 16 arrivals, then 16-arrival root.
// Poll is a plain L2 load. Counters self-reset; g_gen monotonic across replays.
__device__ __forceinline__ void grid_sync(unsigned target, int bid) {
    __syncthreads();
    if (threadIdx.x == 0) {
        __threadfence();
        unsigned* leaf = &g_leaf[(bid & 15) * 64];
        unsigned a = atomicAdd(leaf, 1u);
        if (a == 15u) {
            atomicExch(leaf, 0u);
            unsigned rr = atomicAdd(&g_root, 1u);
            if (rr == 15u) {
                atomicExch(&g_root, 0u);
                __threadfence();
                atomicExch(&g_gen, target);
            }
        }
        while (ldcg_u32(&g_gen) != target) __nanosleep(32);
        __threadfence();
    }
    __syncthreads();
}

// Expand g_adj[row] bitmask into nbr[] (full warp). Returns count.
__device__ __forceinline__ int build_list(int row, int* nbr) {
    int lane = threadIdx.x & 31;
    unsigned word = (lane < 8) ? g_adj[row * 8 + lane] : 0u;
    int pc = __popc(word);
    int inc = pc;
#pragma unroll
    for (int off = 1; off < 8; off <<= 1) {
        int v = __shfl_up_sync(0xffffffffu, inc, off);
        if (lane >= off) inc += v;
    }
    int base = inc - pc;
    if (lane < 8) {
        unsigned bits = word; int o = base;
        while (bits) { int b = __ffs(bits) - 1; bits &= bits - 1; nbr[o++] = lane * 32 + b; }
    }
    return __shfl_sync(0xffffffffu, inc, 7);
}

struct Smem {
    int nbr[2][NN];            // persists P2 -> P3 (bid<128 reuse their rows)
    int cnts[2];
    int selfS[2];
    unsigned gen0;
    __align__(16) union {
        struct { float X[2][DD]; float H[2][DD]; float part[8][2][DD]; } p1; // 10KB
        struct { float U[2][DD]; float D[2][DD];
                 float pU[8][2][DD]; float pD[8][2][DD]; } p2;               // 18KB
        struct { float Ssum[2][DD]; float pS[4][2][DD];
                 float pA[8][2][DD]; float Hs[2][DD]; } p3;                  // 15KB
    } u;
};

__global__ void __launch_bounds__(NT, 2)
k_fused(const int* __restrict__ ei32, int E,
        const float* __restrict__ xf, const float4* __restrict__ w14,
        const float* __restrict__ b1, const float4* __restrict__ w24,
        const float* __restrict__ b2, float* __restrict__ out) {
    __shared__ Smem sm;
    const int tid = threadIdx.x, lane = tid & 31, w = tid >> 5, bid = blockIdx.x;
    const int i    = bid >> 7;                // MLP instance 0/1
    const int row0 = (bid & 127) * 2;         // 2 rows per block
    const int kb   = w * 16;                  // this warp's k-slice
    const float4* x4 = (const float4*)xf;
    const float* w2f = (const float*)w24;

    if (tid == 0) sm.gen0 = ldcg_u32(&g_gen);
    __syncthreads();
    const unsigned gen0 = sm.gen0;

    // ===== P1: edge scatter (blocks 0-7) + p_i = MLP_{0,i}(x) ==============
    if (bid < 8) {
        // dtype sniff: int64 node ids (<256, nonneg) => odd int32 words zero
        int probe = (2 * tid + 1 < 2 * E) ? ei32[2 * tid + 1] : 0;
        int is64 = __syncthreads_and(probe == 0);
        for (int e = bid * NT + tid; e < E; e += 8 * NT) {
            int a, b;
            if (is64) { a = ei32[2 * e]; b = ei32[2 * (E + e)]; }
            else      { a = ei32[e];     b = ei32[E + e]; }
            a &= 255; b &= 255;
            atomicOr(&g_adj[a * 8 + (b >> 5)], 1u << (b & 31));
            atomicOr(&g_adj[b * 8 + (a >> 5)], 1u << (a & 31));
        }
    }
    if (tid < 64) {
        int rr = tid >> 5, ln = tid & 31;
        ((float4*)sm.u.p1.X[rr])[ln] = x4[(row0 + rr) * 32 + ln];
    }
    __syncthreads();
    {   // L1 GEMM, inline fold; each weight pair feeds 2 rows
        float4 acc[2] = {};
#pragma unroll
        for (int kk = 0; kk < 16; kk++) {
            int k = kb + kk;
            float4 wa = w14[i * 8192 + k * 32 + lane];
            float4 wb = w14[i * 8192 + (k + 128) * 32 + lane];
            float4 we = f4add(wa, wb);
            acc[0] = f4fma(sm.u.p1.X[0][k], we, acc[0]);
            acc[1] = f4fma(sm.u.p1.X[1][k], we, acc[1]);
        }
        ((float4*)sm.u.p1.part[w][0])[lane] = acc[0];
        ((float4*)sm.u.p1.part[w][1])[lane] = acc[1];
    }
    __syncthreads();
    {   // H = relu(sum parts + b1[0,i]); 256 vals / 256 threads
        int r = tid >> 7, c = tid & 127;
        float s = b1[i * DD + c];
#pragma unroll
        for (int ww = 0; ww < 8; ww++) s += sm.u.p1.part[ww][r][c];
        __syncthreads();
        sm.u.p1.H[r][c] = fmaxf(s, 0.f);
    }
    __syncthreads();
    {   // L2 GEMM
        float4 acc[2] = {};
#pragma unroll
        for (int kk = 0; kk < 16; kk++) {
            int k = kb + kk;
            float4 wv = w24[i * 4096 + k * 32 + lane];
            acc[0] = f4fma(sm.u.p1.H[0][k], wv, acc[0]);
            acc[1] = f4fma(sm.u.p1.H[1][k], wv, acc[1]);
        }
        ((float4*)sm.u.p1.part[w][0])[lane] = acc[0];
        ((float4*)sm.u.p1.part[w][1])[lane] = acc[1];
    }
    __syncthreads();
    {
        float* dst = i ? g_p1 : g_p0;
        int r = tid >> 7, c = tid & 127;
        float s = b2[i * DD + c];
#pragma unroll
        for (int ww = 0; ww < 8; ww++) s += sm.u.p1.part[ww][r][c];
        dst[(row0 + r) * DD + c] = s;
    }
    grid_sync(gen0 + 1, bid);

    // ===== P2: lists, d, u-gather, {u,d} x W1e[1,i] GEMM (inline fold) =====
    if (w < 2) {                              // warps 0-1: neighbor lists
        int row = row0 + w;
        int cn = build_list(row, sm.nbr[w]);
        if (lane == 0) {
            sm.cnts[w]  = cn;
            sm.selfS[w] = (g_adj[row * 8 + (row >> 5)] >> (row & 31)) & 1;
        }
    } else if (w < 4) {                       // warps 2-3: d = p1 - p0
        int row = row0 + (w - 2);
        float4 p1v = ((const float4*)g_p1)[row * 32 + lane];
        float4 p0v = ((const float4*)g_p0)[row * 32 + lane];
        float4 dv = make_float4(p1v.x - p0v.x, p1v.y - p0v.y,
                                p1v.z - p0v.z, p1v.w - p0v.w);
        ((float4*)sm.u.p2.D[w - 2])[lane] = dv;
        if (i == 0) ((float4*)g_d)[row * 32 + lane] = dv;
    }
    __syncthreads();
    {   // u-gather: warp (r, q) splits list mod 4; partials into pU[q][r]
        const int r = w & 1, q = w >> 1;
        const float4* p04 = (const float4*)g_p0;
        int cn = sm.cnts[r];
        float4 s0 = {}, s1 = {};
        int j = q;
        for (; j + 4 < cn; j += 8) {
            s0 = f4add(s0, p04[sm.nbr[r][j]     * 32 + lane]);
            s1 = f4add(s1, p04[sm.nbr[r][j + 4] * 32 + lane]);
        }
        if (j < cn) s0 = f4add(s0, p04[sm.nbr[r][j] * 32 + lane]);
        ((float4*)sm.u.p2.pU[q][r])[lane] = f4add(s0, s1);
    }
    __syncthreads();
    {   // U = x + gathered partials; 256 vals / 256 threads
        int r = tid >> 7, c = tid & 127;
        float uv = xf[(row0 + r) * DD + c] + sm.u.p2.pU[0][r][c]
                 + sm.u.p2.pU[1][r][c] + sm.u.p2.pU[2][r][c] + sm.u.p2.pU[3][r][c];
        __syncthreads();
        sm.u.p2.U[r][c] = uv;
        if (i == 0) g_u[(row0 + r) * DD + c] = uv;
    }
    __syncthreads();
    {   // GEMM: one folded weight pair feeds U and D for both rows
        float4 aU[2] = {}, aD[2] = {};
#pragma unroll
        for (int kk = 0; kk < 16; kk++) {
            int k = kb + kk;
            float4 wa = w14[(2 + i) * 8192 + k * 32 + lane];
            float4 wb = w14[(2 + i) * 8192 + (k + 128) * 32 + lane];
            float4 we = f4add(wa, wb);
            aU[0] = f4fma(sm.u.p2.U[0][k], we, aU[0]);
            aU[1] = f4fma(sm.u.p2.U[1][k], we, aU[1]);
            aD[0] = f4fma(sm.u.p2.D[0][k], we, aD[0]);
            aD[1] = f4fma(sm.u.p2.D[1][k], we, aD[1]);
        }
#pragma unroll
        for (int r = 0; r < 2; r++) {
            ((float4*)sm.u.p2.pU[w][r])[lane] = aU[r];
            ((float4*)sm.u.p2.pD[w][r])[lane] = aD[r];
        }
    }
    __syncthreads();
    {   // write Un_i / Dt_i: 512 vals / 256 threads
        int r = tid >> 7, c = tid & 127;
        float sU = 0.f, sD = 0.f;
#pragma unroll
        for (int ww = 0; ww < 8; ww++) {
            sU += sm.u.p2.pU[ww][r][c];
            sD += sm.u.p2.pD[ww][r][c];
        }
        g_UD[2 * i    ][(row0 + r) * DD + c] = sU;
        g_UD[2 * i + 1][(row0 + r) * DD + c] = sD;
    }
    grid_sync(gen0 + 2, bid);
    if (bid >= 128) return;                   // lists for these rows live here

    // ===== P3: relu-gather + final matvec + self fix + output ==============
    {
        const int r = w & 1, q = w >> 1;      // split list mod 4
        int row = row0 + r;
        const float4* UD0 = (const float4*)g_UD[0];
        float4 pre = f4add(((const float4*)g_UD[1])[row * 32 + lane],
                           ((const float4*)(b1 + 2 * DD))[lane]);
        int cn = sm.cnts[r];
        float4 s0 = {}, s1 = {};
        int j = q;
        for (; j + 4 < cn; j += 8) {
            s0 = f4add(s0, f4relu(f4add(UD0[sm.nbr[r][j]     * 32 + lane], pre)));
            s1 = f4add(s1, f4relu(f4add(UD0[sm.nbr[r][j + 4] * 32 + lane], pre)));
        }
        if (j < cn) s0 = f4add(s0, f4relu(f4add(UD0[sm.nbr[r][j] * 32 + lane], pre)));
        ((float4*)sm.u.p3.pS[q][r])[lane] = f4add(s0, s1);
    }
    __syncthreads();
    {   // Ssum reduce: 256 vals / 256 threads
        int r = tid >> 7, c = tid & 127;
        sm.u.p3.Ssum[r][c] = sm.u.p3.pS[0][r][c] + sm.u.p3.pS[1][r][c]
                           + sm.u.p3.pS[2][r][c] + sm.u.p3.pS[3][r][c];
    }
    __syncthreads();
    {   // final GEMM vs w2[1,0]
        float4 acc[2] = {};
#pragma unroll
        for (int kk = 0; kk < 16; kk++) {
            int k = kb + kk;
            float4 wv = w24[8192 + k * 32 + lane];
            acc[0] = f4fma(sm.u.p3.Ssum[0][k], wv, acc[0]);
            acc[1] = f4fma(sm.u.p3.Ssum[1][k], wv, acc[1]);
        }
        ((float4*)sm.u.p3.pA[w][0])[lane] = acc[0];
        ((float4*)sm.u.p3.pA[w][1])[lane] = acc[1];
    }
    __syncthreads();
    {   // epilogue: thread owns (r0, c)
        const int r0 = tid >> 7, c = tid & 127;
        int row = row0 + r0;
        float a2 = 0.f;
#pragma unroll
        for (int ww = 0; ww < 8; ww++) a2 += sm.u.p3.pA[ww][r0][c];
        float sf = (float)sm.selfS[r0];
        float res = g_u[row * DD + c] + sf * g_d[row * DD + c]
                  + a2 + (float)sm.cnts[r0] * b2[2 * DD + c];
#pragma unroll
        for (int rr = 0; rr < 2; rr++) {
            if (sm.selfS[rr]) {               // block-uniform, rare (~8/256)
                int rowx = row0 + rr;
                if (tid < 128) {
                    sm.u.p3.Hs[0][tid] = fmaxf(g_UD[0][rowx * DD + tid]
                                              + g_UD[1][rowx * DD + tid]
                                              + b1[2 * DD + tid], 0.f);
                    sm.u.p3.Hs[1][tid] = fmaxf(g_UD[2][rowx * DD + tid]
                                              + g_UD[3][rowx * DD + tid]
                                              + b1[3 * DD + tid], 0.f);
                }
                __syncthreads();
                float d0 = 0.f, d1 = 0.f;
#pragma unroll 4
                for (int k = 0; k < DD; k++) {
                    d0 = fmaf(sm.u.p3.Hs[0][k], w2f[32768 + k * DD + c], d0);
                    d1 = fmaf(sm.u.p3.Hs[1][k], w2f[49152 + k * DD + c], d1);
                }
                if (rr == r0)
                    res += (d1 + b2[3 * DD + c]) - (d0 + b2[2 * DD + c]);
                __syncthreads();
            }
        }
        out[row * DD + c] = res;
    }
    // restore adjacency rows for the next graph replay
    __syncthreads();
    if (tid < 16) g_adj[row0 * 8 + tid] = 0u;
}

extern "C" void kernel_launch(void* const* d_in, const int* in_sizes, int n_in,
                              void* d_out, int out_size) {
    const float* x  = (const float*)d_in[0];
    const float* w1 = (const float*)d_in[1];
    const float* b1 = (const float*)d_in[2];
    const float* w2 = (const float*)d_in[3];
    const float* b2 = (const float*)d_in[4];
    const int*   ei = (const int*)d_in[5];   // dtype sniffed on device
    int E = in_sizes[5] / 2;
    float* out = (float*)d_out;

    k_fused<<<NB, NT>>>(ei, E, x, (const float4*)w1, b1,
                        (const float4*)w2, b2, out);
}